// round 3
// baseline (speedup 1.0000x reference)
#include <cuda_runtime.h>
#include <math.h>

#define N_NODES 100000
#define N_EDGES 1000000
#define N_GRAPHS 128
#define HD 64
#define BN_EPS 1e-5f

// ---------------- scratch (device globals; no allocation allowed) ----------------
__device__ __align__(16) int   g_rowptr[N_NODES + 1];
__device__ __align__(16) int   g_cursor[N_NODES];
__device__ __align__(16) int   g_deg[N_NODES];
__device__ __align__(16) int   g_csrsrc[N_EDGES];
__device__ __align__(16) float g_h[N_NODES * HD];
__device__ __align__(16) float g_y[N_NODES * HD];
__device__ __align__(16) float g_a[N_NODES * HD];
__device__ __align__(16) float g_pool[N_GRAPHS * HD];
__device__ __align__(16) int   g_cnt[N_GRAPHS];

// ---------------- CSR build ----------------
__global__ void k_init() {
    int i = blockIdx.x * blockDim.x + threadIdx.x;
    if (i < N_NODES) g_deg[i] = 0;
    if (i < N_GRAPHS * HD) g_pool[i] = 0.f;
    if (i < N_GRAPHS) g_cnt[i] = 0;
}

__global__ void k_count(const int* __restrict__ ei,
                        const int* __restrict__ batch) {
    int e = blockIdx.x * blockDim.x + threadIdx.x;
    if (e < N_EDGES) {
        int d = ei[N_EDGES + e];  // dst row
        atomicAdd(&g_deg[d], 1);
    }
    if (e < N_NODES) {
        atomicAdd(&g_cnt[batch[e]], 1);
    }
}

// single block, 1024 threads: exclusive scan of degrees -> rowptr, cursor
__global__ void k_scan() {
    __shared__ int warpsum[32];
    int tid = threadIdx.x, lane = tid & 31, wid = tid >> 5;
    int carry = 0;
    if (tid == 0) g_rowptr[0] = 0;
    for (int base = 0; base < N_NODES; base += 1024) {
        int i = base + tid;
        int v = (i < N_NODES) ? g_deg[i] : 0;
        int x = v;
        #pragma unroll
        for (int off = 1; off < 32; off <<= 1) {
            int t = __shfl_up_sync(0xffffffffu, x, off);
            if (lane >= off) x += t;
        }
        if (lane == 31) warpsum[wid] = x;
        __syncthreads();
        if (wid == 0) {
            int w = warpsum[lane];
            #pragma unroll
            for (int off = 1; off < 32; off <<= 1) {
                int t = __shfl_up_sync(0xffffffffu, w, off);
                if (lane >= off) w += t;
            }
            warpsum[lane] = w;
        }
        __syncthreads();
        int woff = (wid > 0) ? warpsum[wid - 1] : 0;
        int incl = x + woff;
        if (i < N_NODES) {
            g_rowptr[i + 1] = carry + incl;
            g_cursor[i] = carry + incl - v;
        }
        carry += warpsum[31];
        __syncthreads();
    }
}

__global__ void k_scatter(const int* __restrict__ ei) {
    int e = blockIdx.x * blockDim.x + threadIdx.x;
    if (e >= N_EDGES) return;
    int d = ei[N_EDGES + e];
    int s = ei[e];
    int p = atomicAdd(&g_cursor[d], 1);
    g_csrsrc[p] = s;
}

// ---------------- GEMM: out[N,64] = A[N, KTILES*64] @ W[KTILES*64, 64] ----------------
// IN_SEL: 0 = external pointer arg, 1 = g_h, 2 = g_a.  OUT_SEL: 0 = g_y, 1 = g_h.
template <int KTILES, bool RELU, int IN_SEL, int OUT_SEL>
__global__ __launch_bounds__(256) void k_gemm(const float* __restrict__ Aext,
                                              const float* __restrict__ W) {
    constexpr int K = KTILES * 64;
    const float* A = (IN_SEL == 0) ? Aext : (IN_SEL == 1 ? (const float*)g_h
                                                         : (const float*)g_a);
    float* out = (OUT_SEL == 0) ? g_y : g_h;

    __shared__ __align__(16) float sA[64][65];
    __shared__ __align__(16) float sW[64][64];
    int row0 = blockIdx.x * 64;
    int tid = threadIdx.x;
    int c0 = (tid & 15) * 4, r0 = (tid >> 4) * 4;
    float acc[4][4] = {};

    for (int kt = 0; kt < KTILES; kt++) {
        // load A chunk: 64 rows x 64 k (1024 float4, 4 per thread)
        #pragma unroll
        for (int it = 0; it < 4; it++) {
            int idx = tid + it * 256;
            int r = idx >> 4, kc = idx & 15;
            int row = row0 + r;
            float4 v = make_float4(0.f, 0.f, 0.f, 0.f);
            if (row < N_NODES)
                v = *(const float4*)(A + (size_t)row * K + kt * 64 + kc * 4);
            sA[r][kc * 4 + 0] = v.x;
            sA[r][kc * 4 + 1] = v.y;
            sA[r][kc * 4 + 2] = v.z;
            sA[r][kc * 4 + 3] = v.w;
        }
        // load W chunk: 64 x 64
        #pragma unroll
        for (int it = 0; it < 4; it++) {
            int idx = tid + it * 256;
            int kk = idx >> 4, cc = idx & 15;
            *(float4*)&sW[kk][cc * 4] =
                *(const float4*)(W + (size_t)(kt * 64 + kk) * 64 + cc * 4);
        }
        __syncthreads();

        #pragma unroll
        for (int k = 0; k < 64; k++) {
            float4 b = *(const float4*)&sW[k][c0];
            #pragma unroll
            for (int i = 0; i < 4; i++) {
                float a = sA[r0 + i][k];
                acc[i][0] += a * b.x;
                acc[i][1] += a * b.y;
                acc[i][2] += a * b.z;
                acc[i][3] += a * b.w;
            }
        }
        __syncthreads();
    }

    #pragma unroll
    for (int i = 0; i < 4; i++) {
        int row = row0 + r0 + i;
        if (row < N_NODES) {
            float4 o;
            o.x = acc[i][0]; o.y = acc[i][1]; o.z = acc[i][2]; o.w = acc[i][3];
            if (RELU) {
                o.x = fmaxf(o.x, 0.f); o.y = fmaxf(o.y, 0.f);
                o.z = fmaxf(o.z, 0.f); o.w = fmaxf(o.w, 0.f);
            }
            *(float4*)(out + (size_t)row * HD + c0) = o;
        }
    }
}

// ---------------- aggregation + BN + relu: g_a[i] = relu(BN(g_y[i] + sum_{e:dst=i} g_y[src[e]]))
__global__ __launch_bounds__(256) void k_agg(const float* __restrict__ gam,
                                             const float* __restrict__ bet,
                                             const float* __restrict__ mea,
                                             const float* __restrict__ var) {
    int gwarp = (blockIdx.x * 256 + threadIdx.x) >> 5;  // one warp per node
    int lane = threadIdx.x & 31;
    if (gwarp >= N_NODES) return;
    const float2* yv = (const float2*)g_y;
    float2 acc = yv[(size_t)gwarp * 32 + lane];
    int beg = g_rowptr[gwarp], end = g_rowptr[gwarp + 1];
    for (int base = beg; base < end; base += 32) {
        int n = end - base;
        if (n > 32) n = 32;
        int idx = (lane < n) ? g_csrsrc[base + lane] : 0;
        int t = 0;
        for (; t + 4 <= n; t += 4) {
            int s0 = __shfl_sync(0xffffffffu, idx, t + 0);
            int s1 = __shfl_sync(0xffffffffu, idx, t + 1);
            int s2 = __shfl_sync(0xffffffffu, idx, t + 2);
            int s3 = __shfl_sync(0xffffffffu, idx, t + 3);
            float2 v0 = yv[(size_t)s0 * 32 + lane];
            float2 v1 = yv[(size_t)s1 * 32 + lane];
            float2 v2 = yv[(size_t)s2 * 32 + lane];
            float2 v3 = yv[(size_t)s3 * 32 + lane];
            acc.x += (v0.x + v1.x) + (v2.x + v3.x);
            acc.y += (v0.y + v1.y) + (v2.y + v3.y);
        }
        for (; t < n; t++) {
            int s = __shfl_sync(0xffffffffu, idx, t);
            float2 v = yv[(size_t)s * 32 + lane];
            acc.x += v.x;
            acc.y += v.y;
        }
    }
    int c0 = lane * 2;
    float i0 = rsqrtf(var[c0] + BN_EPS) * gam[c0];
    float i1 = rsqrtf(var[c0 + 1] + BN_EPS) * gam[c0 + 1];
    float h0 = fmaxf((acc.x - mea[c0]) * i0 + bet[c0], 0.f);
    float h1 = fmaxf((acc.y - mea[c0 + 1]) * i1 + bet[c0 + 1], 0.f);
    ((float2*)g_a)[(size_t)gwarp * 32 + lane] = make_float2(h0, h1);
}

// ---------------- pooling (reads g_h) ----------------
__global__ void k_pool(const int* __restrict__ batch) {
    int idx = blockIdx.x * blockDim.x + threadIdx.x;
    if (idx >= N_NODES * HD) return;
    int i = idx >> 6, c = idx & 63;
    int b = batch[i];
    atomicAdd(&g_pool[b * HD + c], g_h[idx]);
}

// ---------------- final head: mean, lin1+relu, lin2+bias, log_softmax ----------------
__global__ void k_final(const float* __restrict__ lin1, const float* __restrict__ lin2,
                        const float* __restrict__ lb, float* __restrict__ out) {
    __shared__ float sL1[64 * 64];
    __shared__ float sL2[64 * 10];
    __shared__ float sB[10];
    int tid = threadIdx.x;
    for (int i = tid; i < 64 * 64; i += 128) sL1[i] = lin1[i];
    for (int i = tid; i < 64 * 10; i += 128) sL2[i] = lin2[i];
    if (tid < 10) sB[tid] = lb[tid];
    __syncthreads();
    if (tid < N_GRAPHS) {
        float cnt = (float)g_cnt[tid];
        if (cnt < 1.f) cnt = 1.f;
        float pooled[64];
        #pragma unroll
        for (int k = 0; k < 64; k++) pooled[k] = g_pool[tid * 64 + k] / cnt;
        float o[10];
        #pragma unroll
        for (int c = 0; c < 10; c++) o[c] = sB[c];
        for (int j = 0; j < 64; j++) {
            float z = 0.f;
            #pragma unroll
            for (int k = 0; k < 64; k++) z += pooled[k] * sL1[k * 64 + j];
            z = fmaxf(z, 0.f);
            #pragma unroll
            for (int c = 0; c < 10; c++) o[c] += z * sL2[j * 10 + c];
        }
        float mx = o[0];
        #pragma unroll
        for (int c = 1; c < 10; c++) mx = fmaxf(mx, o[c]);
        float se = 0.f;
        #pragma unroll
        for (int c = 0; c < 10; c++) se += expf(o[c] - mx);
        float lse = logf(se) + mx;
        #pragma unroll
        for (int c = 0; c < 10; c++) out[tid * 10 + c] = o[c] - lse;
    }
}

// ---------------- launch (kernel launches ONLY; no other CUDA APIs) ----------------
extern "C" void kernel_launch(void* const* d_in, const int* in_sizes, int n_in,
                              void* d_out, int out_size) {
    const float* x      = (const float*)d_in[0];
    const int*   ei     = (const int*)d_in[1];    // int32 (JAX x64 disabled)
    const int*   batch  = (const int*)d_in[2];    // int32
    const float* W1_0   = (const float*)d_in[3];
    const float* bn_g_0 = (const float*)d_in[4];
    const float* bn_b_0 = (const float*)d_in[5];
    const float* bn_m_0 = (const float*)d_in[6];
    const float* bn_v_0 = (const float*)d_in[7];
    const float* W2_0   = (const float*)d_in[8];
    const float* W1_r   = (const float*)d_in[9];
    const float* bn_g_r = (const float*)d_in[10];
    const float* bn_b_r = (const float*)d_in[11];
    const float* bn_m_r = (const float*)d_in[12];
    const float* bn_v_r = (const float*)d_in[13];
    const float* W2_r   = (const float*)d_in[14];
    const float* lin1   = (const float*)d_in[15];
    const float* lin2   = (const float*)d_in[16];
    const float* lin2b  = (const float*)d_in[17];
    float* out = (float*)d_out;

    const int TPB = 256;
    int gridNodes = (N_NODES + TPB - 1) / TPB;
    int gridEdges = (N_EDGES + TPB - 1) / TPB;
    int gridGemm = (N_NODES + 63) / 64;             // 1563
    int gridAgg = (N_NODES * 32 + TPB - 1) / TPB;   // warp per node
    int gridPool = (N_NODES * HD + TPB - 1) / TPB;

    // CSR build (every launch; deterministic given inputs)
    k_init<<<gridNodes, TPB>>>();
    k_count<<<gridEdges, TPB>>>(ei, batch);
    k_scan<<<1, 1024>>>();
    k_scatter<<<gridEdges, TPB>>>(ei);

    // layer 0: y = x@W1_0 (K=128); a = relu(BN(y+agg(y))); h = relu(a@W2_0)
    k_gemm<2, false, 0, 0><<<gridGemm, TPB>>>(x, W1_0);
    k_agg<<<gridAgg, TPB>>>(bn_g_0, bn_b_0, bn_m_0, bn_v_0);
    k_gemm<1, true, 2, 1><<<gridGemm, TPB>>>(nullptr, W2_0);

    // layers 1..3
    for (int l = 0; l < 3; l++) {
        k_gemm<1, false, 1, 0><<<gridGemm, TPB>>>(nullptr, W1_r + (size_t)l * 64 * 64);
        k_agg<<<gridAgg, TPB>>>(bn_g_r + l * 64, bn_b_r + l * 64,
                                bn_m_r + l * 64, bn_v_r + l * 64);
        k_gemm<1, true, 2, 1><<<gridGemm, TPB>>>(nullptr, W2_r + (size_t)l * 64 * 64);
    }

    // pooling + head
    k_pool<<<gridPool, TPB>>>(batch);
    k_final<<<1, 128>>>(lin1, lin2, lin2b, out);
}

// round 4
// speedup vs baseline: 1.0630x; 1.0630x over previous
#include <cuda_runtime.h>
#include <math.h>

#define N_NODES 100000
#define N_EDGES 1000000
#define N_GRAPHS 128
#define HD 64
#define BN_EPS 1e-5f

// ---------------- scratch (device globals; no allocation allowed) ----------------
__device__ __align__(16) int   g_rowptr[N_NODES + 1];
__device__ __align__(16) int   g_cursor[N_NODES];
__device__ __align__(16) int   g_deg[N_NODES];
__device__ __align__(16) int   g_csrsrc[N_EDGES];
__device__ __align__(16) float g_h[N_NODES * HD];
__device__ __align__(16) float g_y[N_NODES * HD];
__device__ __align__(16) float g_a[N_NODES * HD];
__device__ __align__(16) float g_pool[N_GRAPHS * HD];
__device__ __align__(16) int   g_cnt[N_GRAPHS];

// ---------------- CSR build ----------------
__global__ void k_init() {
    int i = blockIdx.x * blockDim.x + threadIdx.x;
    if (i < N_NODES) g_deg[i] = 0;
    if (i < N_GRAPHS * HD) g_pool[i] = 0.f;
    if (i < N_GRAPHS) g_cnt[i] = 0;
}

__global__ void k_count(const int* __restrict__ ei,
                        const int* __restrict__ batch) {
    int e = blockIdx.x * blockDim.x + threadIdx.x;
    if (e < N_EDGES) {
        atomicAdd(&g_deg[ei[N_EDGES + e]], 1);
    }
    if (e < N_NODES) {
        atomicAdd(&g_cnt[batch[e]], 1);
    }
}

// single block, 1024 threads: exclusive scan of degrees -> rowptr, cursor
__global__ void k_scan() {
    __shared__ int warpsum[32];
    int tid = threadIdx.x, lane = tid & 31, wid = tid >> 5;
    int carry = 0;
    if (tid == 0) g_rowptr[0] = 0;
    for (int base = 0; base < N_NODES; base += 1024) {
        int i = base + tid;
        int v = (i < N_NODES) ? g_deg[i] : 0;
        int x = v;
        #pragma unroll
        for (int off = 1; off < 32; off <<= 1) {
            int t = __shfl_up_sync(0xffffffffu, x, off);
            if (lane >= off) x += t;
        }
        if (lane == 31) warpsum[wid] = x;
        __syncthreads();
        if (wid == 0) {
            int w = warpsum[lane];
            #pragma unroll
            for (int off = 1; off < 32; off <<= 1) {
                int t = __shfl_up_sync(0xffffffffu, w, off);
                if (lane >= off) w += t;
            }
            warpsum[lane] = w;
        }
        __syncthreads();
        int woff = (wid > 0) ? warpsum[wid - 1] : 0;
        int incl = x + woff;
        if (i < N_NODES) {
            g_rowptr[i + 1] = carry + incl;
            g_cursor[i] = carry + incl - v;
        }
        carry += warpsum[31];
        __syncthreads();
    }
}

__global__ void k_scatter(const int* __restrict__ ei) {
    int e = blockIdx.x * blockDim.x + threadIdx.x;
    if (e >= N_EDGES) return;
    int d = ei[N_EDGES + e];
    int s = ei[e];
    int p = atomicAdd(&g_cursor[d], 1);
    g_csrsrc[p] = s;
}

// ---------------- TF32 tensor-core GEMM ----------------
// out[N,64] = A[N, K] @ W[K, 64],  K = KCH*16
// block: 256 threads = 8 warps; block tile 256 rows x 64 cols;
// warp w: rows [w*32, w*32+32) x all 64 cols (2 m-tiles x 8 n-tiles of m16n8k8).
// IN_SEL: 0 = Aext, 1 = g_h, 2 = g_a.  OUT_SEL: 0 = g_y, 1 = g_h.
__device__ __forceinline__ unsigned f2tf(float f) {
    unsigned u;
    asm("cvt.rna.tf32.f32 %0, %1;" : "=r"(u) : "f"(f));
    return u;
}
__device__ __forceinline__ void mma_tf32(float* c, const unsigned* a,
                                         unsigned b0, unsigned b1) {
    asm("mma.sync.aligned.m16n8k8.row.col.f32.tf32.tf32.f32 "
        "{%0,%1,%2,%3},{%4,%5,%6,%7},{%8,%9},{%0,%1,%2,%3};"
        : "+f"(c[0]), "+f"(c[1]), "+f"(c[2]), "+f"(c[3])
        : "r"(a[0]), "r"(a[1]), "r"(a[2]), "r"(a[3]), "r"(b0), "r"(b1));
}

template <int KCH, bool RELU, bool POOL, int IN_SEL, int OUT_SEL>
__global__ __launch_bounds__(256) void k_gemm_tc(const float* __restrict__ Aext,
                                                 const float* __restrict__ W,
                                                 const int* __restrict__ batch) {
    constexpr int K = KCH * 16;
    const float* A = (IN_SEL == 0) ? Aext : (IN_SEL == 1 ? (const float*)g_h
                                                         : (const float*)g_a);
    float* out = (OUT_SEL == 0) ? g_y : g_h;

    __shared__ unsigned sA[256 * 17];  // 256 rows x 16 k, stride 17
    __shared__ unsigned sW[16 * 65];   // 16 k x 64 n, stride 65

    int tid = threadIdx.x;
    int wid = tid >> 5, lane = tid & 31;
    int tg = lane >> 2, tig = lane & 3;  // group, thread-in-group
    int row0 = blockIdx.x * 256;

    float c[2][8][4];
    #pragma unroll
    for (int mt = 0; mt < 2; mt++)
        #pragma unroll
        for (int nt = 0; nt < 8; nt++)
            #pragma unroll
            for (int j = 0; j < 4; j++) c[mt][nt][j] = 0.f;

    for (int ch = 0; ch < KCH; ch++) {
        int kbase = ch * 16;
        // load A chunk: 256 rows x 16 cols (1024 float4)
        #pragma unroll
        for (int i = 0; i < 4; i++) {
            int idx = tid + i * 256;
            int r = idx >> 2, c4 = idx & 3;
            int grow = row0 + r;
            float4 v = make_float4(0.f, 0.f, 0.f, 0.f);
            if (grow < N_NODES)
                v = *(const float4*)(A + (size_t)grow * K + kbase + c4 * 4);
            unsigned* p = &sA[r * 17 + c4 * 4];
            p[0] = f2tf(v.x); p[1] = f2tf(v.y); p[2] = f2tf(v.z); p[3] = f2tf(v.w);
        }
        // load W chunk: 16 k x 64 n (256 float4, 1 per thread)
        {
            int k = tid >> 4, c4 = tid & 15;
            float4 v = *(const float4*)(W + (size_t)(kbase + k) * 64 + c4 * 4);
            unsigned* p = &sW[k * 65 + c4 * 4];
            p[0] = f2tf(v.x); p[1] = f2tf(v.y); p[2] = f2tf(v.z); p[3] = f2tf(v.w);
        }
        __syncthreads();

        #pragma unroll
        for (int ks = 0; ks < 2; ks++) {
            int ko = ks * 8;
            unsigned a[2][4];
            #pragma unroll
            for (int mt = 0; mt < 2; mt++) {
                int rr = wid * 32 + mt * 16 + tg;
                a[mt][0] = sA[rr * 17 + ko + tig];
                a[mt][1] = sA[(rr + 8) * 17 + ko + tig];
                a[mt][2] = sA[rr * 17 + ko + tig + 4];
                a[mt][3] = sA[(rr + 8) * 17 + ko + tig + 4];
            }
            #pragma unroll
            for (int nt = 0; nt < 8; nt++) {
                unsigned b0 = sW[(ko + tig) * 65 + nt * 8 + tg];
                unsigned b1 = sW[(ko + tig + 4) * 65 + nt * 8 + tg];
                mma_tf32(c[0][nt], a[0], b0, b1);
                mma_tf32(c[1][nt], a[1], b0, b1);
            }
        }
        __syncthreads();
    }

    // epilogue: c0,c1 -> (row, col..col+1); c2,c3 -> (row+8, col..col+1)
    #pragma unroll
    for (int mt = 0; mt < 2; mt++) {
        int row = row0 + wid * 32 + mt * 16 + tg;
        #pragma unroll
        for (int half = 0; half < 2; half++) {
            int r = row + half * 8;
            if (r < N_NODES) {
                int b = POOL ? batch[r] : 0;
                #pragma unroll
                for (int nt = 0; nt < 8; nt++) {
                    int col = nt * 8 + tig * 2;
                    float v0 = c[mt][nt][half * 2 + 0];
                    float v1 = c[mt][nt][half * 2 + 1];
                    if (RELU) { v0 = fmaxf(v0, 0.f); v1 = fmaxf(v1, 0.f); }
                    if (POOL) {
                        atomicAdd(&g_pool[b * HD + col], v0);
                        atomicAdd(&g_pool[b * HD + col + 1], v1);
                    } else {
                        *(float2*)(out + (size_t)r * HD + col) = make_float2(v0, v1);
                    }
                }
            }
        }
    }
}

// ---------------- aggregation + BN + relu: g_a[i] = relu(BN(g_y[i] + sum_{e:dst=i} g_y[src[e]]))
__global__ __launch_bounds__(256) void k_agg(const float* __restrict__ gam,
                                             const float* __restrict__ bet,
                                             const float* __restrict__ mea,
                                             const float* __restrict__ var) {
    int gwarp = (blockIdx.x * 256 + threadIdx.x) >> 5;  // one warp per node
    int lane = threadIdx.x & 31;
    if (gwarp >= N_NODES) return;
    const float2* yv = (const float2*)g_y;
    float2 acc = yv[(size_t)gwarp * 32 + lane];
    int beg = g_rowptr[gwarp], end = g_rowptr[gwarp + 1];
    for (int base = beg; base < end; base += 32) {
        int n = end - base;
        if (n > 32) n = 32;
        int idx = (lane < n) ? g_csrsrc[base + lane] : 0;
        int t = 0;
        for (; t + 4 <= n; t += 4) {
            int s0 = __shfl_sync(0xffffffffu, idx, t + 0);
            int s1 = __shfl_sync(0xffffffffu, idx, t + 1);
            int s2 = __shfl_sync(0xffffffffu, idx, t + 2);
            int s3 = __shfl_sync(0xffffffffu, idx, t + 3);
            float2 v0 = yv[(size_t)s0 * 32 + lane];
            float2 v1 = yv[(size_t)s1 * 32 + lane];
            float2 v2 = yv[(size_t)s2 * 32 + lane];
            float2 v3 = yv[(size_t)s3 * 32 + lane];
            acc.x += (v0.x + v1.x) + (v2.x + v3.x);
            acc.y += (v0.y + v1.y) + (v2.y + v3.y);
        }
        for (; t < n; t++) {
            int s = __shfl_sync(0xffffffffu, idx, t);
            float2 v = yv[(size_t)s * 32 + lane];
            acc.x += v.x;
            acc.y += v.y;
        }
    }
    int c0 = lane * 2;
    float i0 = rsqrtf(var[c0] + BN_EPS) * gam[c0];
    float i1 = rsqrtf(var[c0 + 1] + BN_EPS) * gam[c0 + 1];
    float h0 = fmaxf((acc.x - mea[c0]) * i0 + bet[c0], 0.f);
    float h1 = fmaxf((acc.y - mea[c0 + 1]) * i1 + bet[c0 + 1], 0.f);
    ((float2*)g_a)[(size_t)gwarp * 32 + lane] = make_float2(h0, h1);
}

// ---------------- final head: mean, lin1+relu, lin2+bias, log_softmax ----------------
__global__ void k_final(const float* __restrict__ lin1, const float* __restrict__ lin2,
                        const float* __restrict__ lb, float* __restrict__ out) {
    __shared__ float sL1[64 * 64];
    __shared__ float sL2[64 * 10];
    __shared__ float sB[10];
    int tid = threadIdx.x;
    for (int i = tid; i < 64 * 64; i += 128) sL1[i] = lin1[i];
    for (int i = tid; i < 64 * 10; i += 128) sL2[i] = lin2[i];
    if (tid < 10) sB[tid] = lb[tid];
    __syncthreads();
    if (tid < N_GRAPHS) {
        float cnt = (float)g_cnt[tid];
        if (cnt < 1.f) cnt = 1.f;
        float pooled[64];
        #pragma unroll
        for (int k = 0; k < 64; k++) pooled[k] = g_pool[tid * 64 + k] / cnt;
        float o[10];
        #pragma unroll
        for (int c = 0; c < 10; c++) o[c] = sB[c];
        for (int j = 0; j < 64; j++) {
            float z = 0.f;
            #pragma unroll
            for (int k = 0; k < 64; k++) z += pooled[k] * sL1[k * 64 + j];
            z = fmaxf(z, 0.f);
            #pragma unroll
            for (int c = 0; c < 10; c++) o[c] += z * sL2[j * 10 + c];
        }
        float mx = o[0];
        #pragma unroll
        for (int c = 1; c < 10; c++) mx = fmaxf(mx, o[c]);
        float se = 0.f;
        #pragma unroll
        for (int c = 0; c < 10; c++) se += expf(o[c] - mx);
        float lse = logf(se) + mx;
        #pragma unroll
        for (int c = 0; c < 10; c++) out[tid * 10 + c] = o[c] - lse;
    }
}

// ---------------- launch (kernel launches ONLY; no other CUDA APIs) ----------------
extern "C" void kernel_launch(void* const* d_in, const int* in_sizes, int n_in,
                              void* d_out, int out_size) {
    const float* x      = (const float*)d_in[0];
    const int*   ei     = (const int*)d_in[1];    // int32 (JAX x64 disabled)
    const int*   batch  = (const int*)d_in[2];    // int32
    const float* W1_0   = (const float*)d_in[3];
    const float* bn_g_0 = (const float*)d_in[4];
    const float* bn_b_0 = (const float*)d_in[5];
    const float* bn_m_0 = (const float*)d_in[6];
    const float* bn_v_0 = (const float*)d_in[7];
    const float* W2_0   = (const float*)d_in[8];
    const float* W1_r   = (const float*)d_in[9];
    const float* bn_g_r = (const float*)d_in[10];
    const float* bn_b_r = (const float*)d_in[11];
    const float* bn_m_r = (const float*)d_in[12];
    const float* bn_v_r = (const float*)d_in[13];
    const float* W2_r   = (const float*)d_in[14];
    const float* lin1   = (const float*)d_in[15];
    const float* lin2   = (const float*)d_in[16];
    const float* lin2b  = (const float*)d_in[17];
    float* out = (float*)d_out;

    const int TPB = 256;
    int gridNodes = (N_NODES + TPB - 1) / TPB;
    int gridEdges = (N_EDGES + TPB - 1) / TPB;
    int gridGemm = (N_NODES + 255) / 256;           // 391 (256-row tiles)
    int gridAgg = (N_NODES * 32 + TPB - 1) / TPB;   // warp per node

    // CSR build
    k_init<<<gridNodes, TPB>>>();
    k_count<<<gridEdges, TPB>>>(ei, batch);
    k_scan<<<1, 1024>>>();
    k_scatter<<<gridEdges, TPB>>>(ei);

    // layer 0: y = x@W1_0 (K=128); a = relu(BN(y+agg(y))); h = relu(a@W2_0)
    k_gemm_tc<8, false, false, 0, 0><<<gridGemm, TPB>>>(x, W1_0, nullptr);
    k_agg<<<gridAgg, TPB>>>(bn_g_0, bn_b_0, bn_m_0, bn_v_0);
    k_gemm_tc<4, true, false, 2, 1><<<gridGemm, TPB>>>(nullptr, W2_0, nullptr);

    // layers 1..2
    for (int l = 0; l < 2; l++) {
        k_gemm_tc<4, false, false, 1, 0><<<gridGemm, TPB>>>(nullptr, W1_r + (size_t)l * 64 * 64, nullptr);
        k_agg<<<gridAgg, TPB>>>(bn_g_r + l * 64, bn_b_r + l * 64,
                                bn_m_r + l * 64, bn_v_r + l * 64);
        k_gemm_tc<4, true, false, 2, 1><<<gridGemm, TPB>>>(nullptr, W2_r + (size_t)l * 64 * 64, nullptr);
    }

    // layer 3: last GEMM fuses relu + mean-pool accumulation (skips writing h)
    k_gemm_tc<4, false, false, 1, 0><<<gridGemm, TPB>>>(nullptr, W1_r + (size_t)2 * 64 * 64, nullptr);
    k_agg<<<gridAgg, TPB>>>(bn_g_r + 2 * 64, bn_b_r + 2 * 64,
                            bn_m_r + 2 * 64, bn_v_r + 2 * 64);
    k_gemm_tc<4, true, true, 2, 1><<<gridGemm, TPB>>>(nullptr, W2_r + (size_t)2 * 64 * 64, batch);

    // head
    k_final<<<1, 128>>>(lin1, lin2, lin2b, out);
}